// round 15
// baseline (speedup 1.0000x reference)
#include <cuda_runtime.h>
#include <math.h>

#define B_  4
#define L_  512
#define H_  8
#define D_  64
#define DM_ 512
#define BL_ 2048
#define LL_ (512*512)          // 262144
#define HLL_ (8*512*512)       // 2097152

// ---------------- scratch (device globals; no allocation allowed) -------------
__device__ float g_qs[BL_*DM_];
__device__ float g_kh[BL_*DM_];
__device__ float g_vh[BL_*DM_];
__device__ float g_qc[BL_*DM_];
__device__ float g_self[BL_*DM_];
__device__ float g_sdd[BL_*DM_];
__device__ float g_x[BL_*DM_];
__device__ float g_nw[BL_];
__device__ float g_den[BL_];

__device__ __forceinline__ float gelu_t(float x){
    float u = 0.7978845608028654f*(x + 0.044715f*x*x*x);
    return 0.5f*x*(1.0f + tanhf(u));
}

// ---------------- generic tiled SGEMM: C(tile 64x64) = A[MxK] @ B[KxN] -------
// EPI: 0 = C = acc*scale
//      1 = C += acc
//      2 = C = acc * aux0[z*M+row]                 (row scale, e.g. node_weight)
//      3 = C = aux0[ci] + acc / aux1[z*M+row]      (self + agg/denom)
//      4 = C = aux0[ci] + gelu(acc)                (residual + gelu)
// TB:  B accessed transposed (C = A @ B^T, B row-major [N x K])
// AINT: A is int32, converted to float on load
template<int EPI, bool TB, bool AINT>
__global__ __launch_bounds__(256) void gemm_k(
    const float* __restrict__ A, int lda, long sA1, long sA2,
    const float* __restrict__ B, int ldb, long sB1, long sB2,
    float* __restrict__ C, int ldc, long sC1, long sC2,
    int M, int N, int K, int zinner,
    const float* __restrict__ aux0, const float* __restrict__ aux1,
    float scale)
{
    __shared__ float As[16][68];
    __shared__ float Bs[16][68];
    int z = blockIdx.z;
    int zo = z / zinner, zi = z - zo*zinner;
    A += zo*sA1 + zi*sA2;
    B += zo*sB1 + zi*sB2;
    C += zo*sC1 + zi*sC2;
    if (EPI==3 || EPI==4) aux0 += zo*sC1 + zi*sC2;

    int n0 = blockIdx.x*64, m0 = blockIdx.y*64;
    int t = threadIdx.x, tx = t & 15, ty = t >> 4;
    float acc[4][4] = {};

    for (int k0 = 0; k0 < K; k0 += 16){
        #pragma unroll
        for (int i = 0; i < 4; i++){
            int e = t + i*256;
            int r = e >> 4, c = e & 15;
            float av;
            if (AINT) av = (float)((const int*)A)[(size_t)(m0+r)*lda + k0 + c];
            else      av = A[(size_t)(m0+r)*lda + k0 + c];
            As[c][r] = av;
        }
        #pragma unroll
        for (int i = 0; i < 4; i++){
            int e = t + i*256;
            if (TB){
                int nn = e >> 4, kk = e & 15;
                Bs[kk][nn] = B[(size_t)(n0+nn)*ldb + k0 + kk];
            } else {
                int kk = e >> 6, nn = e & 63;
                Bs[kk][nn] = B[(size_t)(k0+kk)*ldb + n0 + nn];
            }
        }
        __syncthreads();
        #pragma unroll
        for (int kk = 0; kk < 16; kk++){
            float4 a = *(const float4*)&As[kk][ty*4];
            float4 b = *(const float4*)&Bs[kk][tx*4];
            float av[4] = {a.x, a.y, a.z, a.w};
            float bv[4] = {b.x, b.y, b.z, b.w};
            #pragma unroll
            for (int i = 0; i < 4; i++)
                #pragma unroll
                for (int j = 0; j < 4; j++)
                    acc[i][j] += av[i]*bv[j];
        }
        __syncthreads();
    }

    #pragma unroll
    for (int i = 0; i < 4; i++){
        int grow = m0 + ty*4 + i;
        #pragma unroll
        for (int j = 0; j < 4; j++){
            int gcol = n0 + tx*4 + j;
            size_t ci = (size_t)grow*ldc + gcol;
            float v = acc[i][j];
            if (EPI==0)      C[ci] = v*scale;
            else if (EPI==1) C[ci] += v;
            else if (EPI==2) C[ci] = v * aux0[(size_t)z*M + grow];
            else if (EPI==3) C[ci] = aux0[ci] + v / aux1[(size_t)z*M + grow];
            else if (EPI==4) C[ci] = aux0[ci] + gelu_t(v);
        }
    }
}

// -------- rel-pos K scores + mask + softmax, one block per (b,l) -------------
// attn buffer holds content scores on entry (written by the QK^T GEMM);
// this kernel adds qs . vec_adj_k, applies the adjacency mask, softmaxes,
// and writes the final attention back.
__global__ __launch_bounds__(256) void relk_softmax_kernel(
    const float* __restrict__ qs, const float* __restrict__ vak,
    const int* __restrict__ adj, float* __restrict__ attn)
{
    __shared__ float sc[8][512];
    __shared__ float qrow[512];
    int bl = blockIdx.x;
    int b = bl >> 9, l = bl & 511;
    int t = threadIdx.x;

    qrow[t]       = qs[(size_t)bl*512 + t];
    qrow[t + 256] = qs[(size_t)bl*512 + t + 256];
    __syncthreads();

    int m0 = t, m1 = t + 256;
    size_t abase = (size_t)b*HLL_ + (size_t)l*512;
    float acc0[8], acc1[8];
    #pragma unroll
    for (int h = 0; h < 8; h++){
        acc0[h] = attn[abase + (size_t)h*LL_ + m0];
        acc1[h] = attn[abase + (size_t)h*LL_ + m1];
    }
    const float4* v0 = (const float4*)(vak + ((size_t)bl*512 + m0)*64);
    const float4* v1 = (const float4*)(vak + ((size_t)bl*512 + m1)*64);
    #pragma unroll
    for (int d4 = 0; d4 < 16; d4++){
        float4 a = v0[d4];
        float4 c = v1[d4];
        #pragma unroll
        for (int h = 0; h < 8; h++){
            float4 q = *(const float4*)&qrow[h*64 + d4*4];
            acc0[h] += q.x*a.x + q.y*a.y + q.z*a.z + q.w*a.w;
            acc1[h] += q.x*c.x + q.y*c.y + q.z*c.z + q.w*c.w;
        }
    }
    #pragma unroll
    for (int h = 0; h < 8; h++){ sc[h][m0] = acc0[h]; sc[h][m1] = acc1[h]; }
    __syncthreads();

    // warp w handles head h = w; lane covers m = lane + j*32
    int w = t >> 5, lane = t & 31;
    const int* arow = adj + (size_t)bl*512;
    float vals[16];
    float mx = -1e30f;
    #pragma unroll
    for (int j = 0; j < 16; j++){
        int m = lane + j*32;
        float s = (arow[m] == 0) ? -10000.0f : sc[w][m];
        vals[j] = s;
        mx = fmaxf(mx, s);
    }
    #pragma unroll
    for (int o = 16; o; o >>= 1) mx = fmaxf(mx, __shfl_xor_sync(0xffffffffu, mx, o));
    float sum = 0.f;
    #pragma unroll
    for (int j = 0; j < 16; j++){ vals[j] = __expf(vals[j] - mx); sum += vals[j]; }
    #pragma unroll
    for (int o = 16; o; o >>= 1) sum += __shfl_xor_sync(0xffffffffu, sum, o);
    float inv = 1.0f / sum;
    float* arow_out = attn + abase + (size_t)w*LL_;
    #pragma unroll
    for (int j = 0; j < 16; j++) arow_out[lane + j*32] = vals[j]*inv;
}

// -------- rel-pos V: qc[b,l,h*64+d] = sum_m attn[b,h,l,m]*vec_adj_v[b,l,m,d] --
__global__ __launch_bounds__(256) void relv_kernel(
    const float* __restrict__ attn, const float* __restrict__ vav,
    float* __restrict__ qc)
{
    __shared__ float smem[8192];        // 32KB: attn_sm (16KB) then reduction
    float* attn_sm = smem;              // layout [m][h], 512*8
    int bl = blockIdx.x;
    int b = bl >> 9, l = bl & 511;
    int t = threadIdx.x;
    size_t abase = (size_t)b*HLL_ + (size_t)l*512;
    #pragma unroll
    for (int i = 0; i < 16; i++){
        int e = t + i*256;
        int h = e >> 9, m = e & 511;
        attn_sm[m*8 + h] = attn[abase + (size_t)h*LL_ + m];
    }
    __syncthreads();

    int dq = t & 15, g = t >> 4;        // 16 d-quads x 16 m-groups (32 m each)
    const float4* vv = (const float4*)(vav + ((size_t)bl*512 + (size_t)g*32)*64) + dq;
    float4 acc[8];
    #pragma unroll
    for (int h = 0; h < 8; h++) acc[h] = make_float4(0.f,0.f,0.f,0.f);

    #pragma unroll 4
    for (int mm = 0; mm < 32; mm++){
        float4 v = vv[(size_t)mm*16];
        const float4* ap = (const float4*)&attn_sm[(g*32 + mm)*8];
        float4 a0 = ap[0], a1 = ap[1];
        #define FMA4(A_, s_) { A_.x += (s_)*v.x; A_.y += (s_)*v.y; A_.z += (s_)*v.z; A_.w += (s_)*v.w; }
        FMA4(acc[0], a0.x) FMA4(acc[1], a0.y) FMA4(acc[2], a0.z) FMA4(acc[3], a0.w)
        FMA4(acc[4], a1.x) FMA4(acc[5], a1.y) FMA4(acc[6], a1.z) FMA4(acc[7], a1.w)
        #undef FMA4
    }
    __syncthreads();                    // attn_sm no longer needed
    float4* red = (float4*)smem;        // [g][h][dq] float4 = 2048 float4 = 32KB
    #pragma unroll
    for (int h = 0; h < 8; h++) red[(g*8 + h)*16 + dq] = acc[h];
    __syncthreads();
    if (t < 128){
        int h = t >> 4, d2 = t & 15;
        float4 s = make_float4(0.f,0.f,0.f,0.f);
        #pragma unroll
        for (int g2 = 0; g2 < 16; g2++){
            float4 r = red[(g2*8 + h)*16 + d2];
            s.x += r.x; s.y += r.y; s.z += r.z; s.w += r.w;
        }
        *(float4*)&qc[(size_t)bl*512 + h*64 + d2*4] = s;
    }
}

// -------- node_weight = sigmoid(qc @ w_nw), denom = max(sum(adj_row),1) ------
__global__ __launch_bounds__(128) void node_kernel(
    const float* __restrict__ qc, const float* __restrict__ w_nw,
    const int* __restrict__ adj, float* __restrict__ nw, float* __restrict__ den)
{
    int bl = blockIdx.x, t = threadIdx.x;
    float d = 0.f, a = 0.f;
    for (int c = t; c < 512; c += 128){
        d += qc[(size_t)bl*512 + c] * w_nw[c];
        a += (float)adj[(size_t)bl*512 + c];
    }
    __shared__ float sd[128], sa[128];
    sd[t] = d; sa[t] = a; __syncthreads();
    for (int s = 64; s; s >>= 1){
        if (t < s){ sd[t] += sd[t+s]; sa[t] += sa[t+s]; }
        __syncthreads();
    }
    if (t == 0){
        nw[bl] = 1.0f/(1.0f + expf(-sd[0]));
        float s = sa[0];
        den[bl] = (s >= 1.0f) ? s : 1.0f;
    }
}

// ------------------------------- launcher ------------------------------------
extern "C" void kernel_launch(void* const* d_in, const int* in_sizes, int n_in,
                              void* d_out, int out_size)
{
    const float* q      = (const float*)d_in[0];
    const float* k      = (const float*)d_in[1];
    const float* v      = (const float*)d_in[2];
    const float* vak    = (const float*)d_in[3];
    const float* vav    = (const float*)d_in[4];
    const int*   adjk   = (const int*)  d_in[5];
    // d_in[6] = adj_v (unused by reference)
    const float* w_qs   = (const float*)d_in[7];
    const float* w_ks   = (const float*)d_in[8];
    const float* w_vs   = (const float*)d_in[9];
    const float* w_fc   = (const float*)d_in[10];
    const float* w_nw   = (const float*)d_in[11];
    const float* w_self = (const float*)d_in[12];
    const float* w_dd   = (const float*)d_in[13];

    float* out  = (float*)d_out;
    float* qo   = out;                      // [B,L,512]   = 1,048,576
    float* attn = out + (size_t)BL_*DM_;    // [B,H,L,L]   = 8,388,608

    float *qs, *kh, *vh, *qc, *selfp, *sdd, *xb, *nw, *den;
    cudaGetSymbolAddress((void**)&qs,    g_qs);
    cudaGetSymbolAddress((void**)&kh,    g_kh);
    cudaGetSymbolAddress((void**)&vh,    g_vh);
    cudaGetSymbolAddress((void**)&qc,    g_qc);
    cudaGetSymbolAddress((void**)&selfp, g_self);
    cudaGetSymbolAddress((void**)&sdd,   g_sdd);
    cudaGetSymbolAddress((void**)&xb,    g_x);
    cudaGetSymbolAddress((void**)&nw,    g_nw);
    cudaGetSymbolAddress((void**)&den,   g_den);

    dim3 blk(256);

    // 1-3: projections (qs pre-scaled by 1/sqrt(Dk)=0.125)
    gemm_k<0,false,false><<<dim3(8,32,1), blk>>>(q,512,0,0, w_qs,512,0,0, qs,512,0,0,
                                                 2048,512,512, 1, nullptr,nullptr, 0.125f);
    gemm_k<0,false,false><<<dim3(8,32,1), blk>>>(k,512,0,0, w_ks,512,0,0, kh,512,0,0,
                                                 2048,512,512, 1, nullptr,nullptr, 1.0f);
    gemm_k<0,false,false><<<dim3(8,32,1), blk>>>(v,512,0,0, w_vs,512,0,0, vh,512,0,0,
                                                 2048,512,512, 1, nullptr,nullptr, 1.0f);

    // 4: content scores = qs @ kh^T (batched over b,h) -> attn buffer
    gemm_k<0,true,false><<<dim3(8,8,32), blk>>>(qs,512, (long)L_*DM_, 64,
                                                kh,512, (long)L_*DM_, 64,
                                                attn,512, (long)HLL_, (long)LL_,
                                                512,512,64, 8, nullptr,nullptr, 1.0f);

    // 5: add rel-pos K scores, mask, softmax (in-place in attn)
    relk_softmax_kernel<<<BL_, 256>>>(qs, vak, adjk, attn);

    // 6: rel-pos V part -> qc (fresh write)
    relv_kernel<<<BL_, 256>>>(attn, vav, qc);

    // 7: qc += attn @ vh (batched over b,h)
    gemm_k<1,false,false><<<dim3(1,8,32), blk>>>(attn,512, (long)HLL_, (long)LL_,
                                                 vh,512, (long)L_*DM_, 64,
                                                 qc,512, (long)L_*DM_, 64,
                                                 512,64,512, 8, nullptr,nullptr, 1.0f);

    // 8: node_weight, denom
    node_kernel<<<BL_, 128>>>(qc, w_nw, adjk, nw, den);

    // 9: self_info = qc @ w_self
    gemm_k<0,false,false><<<dim3(8,32,1), blk>>>(qc,512,0,0, w_self,512,0,0, selfp,512,0,0,
                                                 2048,512,512, 1, nullptr,nullptr, 1.0f);

    // 10: scaled dd_info = node_weight[row] * (qc @ w_dd)
    gemm_k<2,false,false><<<dim3(8,32,1), blk>>>(qc,512,0,0, w_dd,512,0,0, sdd,512,0,0,
                                                 2048,512,512, 1, nw,nullptr, 1.0f);

    // 11: x = self_info + (adj @ sdd)/denom   (batched over b; A is int adj)
    gemm_k<3,false,true><<<dim3(8,8,4), blk>>>((const float*)adjk,512, (long)LL_, 0,
                                               sdd,512, (long)L_*DM_, 0,
                                               xb,512, (long)L_*DM_, 0,
                                               512,512,512, 1, selfp, den, 1.0f);

    // 12: qo = q + gelu(x @ w_fc)
    gemm_k<4,false,false><<<dim3(8,32,1), blk>>>(xb,512,0,0, w_fc,512,0,0, qo,512,0,0,
                                                 2048,512,512, 1, q,nullptr, 1.0f);

    (void)in_sizes; (void)n_in; (void)out_size;
}